// round 4
// baseline (speedup 1.0000x reference)
#include <cuda_runtime.h>
#include <cuda_bf16.h>
#include <math.h>
#include <stdint.h>

// Problem constants
#define Bz 4
#define Tz 2048
#define DM 1024
#define Hz 16
#define DI 64
#define ROWS (Bz*Tz)            // 8192
#define SQRT_DM 32.0f

typedef __nv_bfloat16 bf16;

// ---------------------------------------------------------------------------
// Scratch (static device globals; no allocations allowed)
// ---------------------------------------------------------------------------
__device__ float g_qkv_raw[(size_t)ROWS * 3 * DM];        // [8192, 3072]
__device__ float g_Q[(size_t)Bz * Hz * Tz * DI];          // [B,H,T,di]
__device__ float g_K[(size_t)Bz * Hz * Tz * DI];
__device__ float g_V[(size_t)Bz * Hz * Tz * DI];
__device__ float g_t[(size_t)ROWS * DM];
__device__ float g_x1[(size_t)ROWS * DM];
__device__ float g_uv[(size_t)ROWS * 8 * DM];             // [8192,8192]

// bf16 hi/lo scratch for tensor-core GEMM operands
__device__ bf16 g_x_h[(size_t)ROWS * DM],      g_x_l[(size_t)ROWS * DM];
__device__ bf16 g_qkvw_h[(size_t)3 * DM * DM], g_qkvw_l[(size_t)3 * DM * DM];
__device__ bf16 g_Wo_h[(size_t)DM * DM],       g_Wo_l[(size_t)DM * DM];
__device__ bf16 g_Wu_h[(size_t)8 * DM * DM],   g_Wu_l[(size_t)8 * DM * DM];
__device__ bf16 g_Wv_h[(size_t)DM * 4 * DM],   g_Wv_l[(size_t)DM * 4 * DM];
__device__ bf16 g_attn_h[(size_t)ROWS * DM],   g_attn_l[(size_t)ROWS * DM];
__device__ bf16 g_x1_h[(size_t)ROWS * DM],     g_x1_l[(size_t)ROWS * DM];
__device__ bf16 g_res_h[(size_t)ROWS * 4 * DM], g_res_l[(size_t)ROWS * 4 * DM];

// ---------------------------------------------------------------------------
// fp32 -> bf16 hi/lo split conversion
// ---------------------------------------------------------------------------
__global__ __launch_bounds__(256) void convert_hl(
    const float* __restrict__ s, bf16* __restrict__ h, bf16* __restrict__ l, int n)
{
    int i = blockIdx.x * 256 + threadIdx.x;
    if (i < n) {
        float v = s[i];
        bf16 hh = __float2bfloat16(v);
        h[i] = hh;
        l[i] = __float2bfloat16(v - __bfloat162float(hh));
    }
}

// ---------------------------------------------------------------------------
// bf16x3 tensor-core GEMM:  C[M,N] = A[M,K] @ B[N,K]^T  (fp32-accurate)
//   A ~ Ah + Al, B ~ Bh + Bl (bf16 splits).  acc += Ah*Bh + Ah*Bl + Al*Bh
// BM=BN=128, BK=64, 512 threads (16 warps, 4x4), warp tile 32x32.
// SW128 swizzled smem, cp.async 3-stage pipeline.
// ---------------------------------------------------------------------------
#define SWZ(off) ((off) ^ (((off) >> 3) & 0x70))
#define GSM_TILE  16384
#define GSM_STAGE 65536
#define GSM_TOTAL (3 * GSM_STAGE)     // 196608

__device__ __forceinline__ void cpasync16(uint32_t dst, const void* src) {
    asm volatile("cp.async.cg.shared.global [%0], [%1], 16;\n" :: "r"(dst), "l"(src));
}
__device__ __forceinline__ void cp_commit() { asm volatile("cp.async.commit_group;\n"); }
template<int N> __device__ __forceinline__ void cp_wait() {
    asm volatile("cp.async.wait_group %0;\n" :: "n"(N));
}
__device__ __forceinline__ void ldsm4(uint32_t& r0, uint32_t& r1, uint32_t& r2, uint32_t& r3, uint32_t a) {
    asm volatile("ldmatrix.sync.aligned.m8n8.x4.shared.b16 {%0,%1,%2,%3}, [%4];"
                 : "=r"(r0), "=r"(r1), "=r"(r2), "=r"(r3) : "r"(a));
}
__device__ __forceinline__ void mma_bf16(float* d, const uint32_t* a, uint32_t b0, uint32_t b1) {
    asm volatile("mma.sync.aligned.m16n8k16.row.col.f32.bf16.bf16.f32 "
                 "{%0,%1,%2,%3}, {%4,%5,%6,%7}, {%8,%9}, {%0,%1,%2,%3};"
                 : "+f"(d[0]), "+f"(d[1]), "+f"(d[2]), "+f"(d[3])
                 : "r"(a[0]), "r"(a[1]), "r"(a[2]), "r"(a[3]), "r"(b0), "r"(b1));
}

// 512 threads: each thread loads 2x16B per tile, 4 tiles per stage (64KB)
#define LOAD_STAGE(sbuf, k0)                                                   \
    do {                                                                       \
        uint32_t _sb = sm0 + (uint32_t)(sbuf) * GSM_STAGE;                     \
        _Pragma("unroll")                                                      \
        for (int _t = 0; _t < 4; _t++) {                                       \
            const bf16* _g = tp[_t] + (k0);                                    \
            uint32_t _sbt = _sb + _t * GSM_TILE;                               \
            _Pragma("unroll")                                                  \
            for (int _u = 0; _u < 2; _u++) {                                   \
                int _c = (tid & 3) + _u * 4;                                   \
                int _r = tid >> 2;                                             \
                uint32_t _off = (uint32_t)(_r * 128 + _c * 16);                \
                cpasync16(_sbt + SWZ(_off), _g + (size_t)_r * K + _c * 8);     \
            }                                                                  \
        }                                                                      \
    } while (0)

__global__ __launch_bounds__(512, 1) void gemm_bf16x3(
    const bf16* __restrict__ Ah, const bf16* __restrict__ Al,
    const bf16* __restrict__ Bh, const bf16* __restrict__ Bl,
    float* __restrict__ C, int M, int N, int K)
{
    extern __shared__ __align__(1024) unsigned char smraw[];
    uint32_t sm0 = (uint32_t)__cvta_generic_to_shared(smraw);

    const int tid = threadIdx.x, lane = tid & 31, wid = tid >> 5;
    const int wm = wid >> 2, wn = wid & 3;           // 4x4 warp grid
    const int bn = blockIdx.x, bm = blockIdx.y;

    const size_t aoff = (size_t)bm * 128 * K;
    const size_t boff = (size_t)bn * 128 * K;
    const bf16* tp[4] = { Ah + aoff, Al + aoff, Bh + boff, Bl + boff };

    float acc[2][4][4];
    #pragma unroll
    for (int a = 0; a < 2; a++)
        #pragma unroll
        for (int b = 0; b < 4; b++)
            #pragma unroll
            for (int c = 0; c < 4; c++) acc[a][b][c] = 0.f;

    // ldmatrix per-lane offsets (A: m16 tiles; B: n16 tiles, two n8 halves)
    const int rowA = lane & 15;
    const uint32_t aCol = (uint32_t)((lane >> 4) * 16);
    const uint32_t aX   = (uint32_t)((rowA & 7) << 4);
    uint32_t aRow[2];
    #pragma unroll
    for (int mi = 0; mi < 2; mi++)
        aRow[mi] = (uint32_t)((wm * 32 + mi * 16 + rowA) * 128);

    const int rowB = ((lane >> 4) << 3) | (lane & 7);
    const uint32_t bCol = (uint32_t)(((lane >> 3) & 1) * 16);
    const uint32_t bX   = (uint32_t)((rowB & 7) << 4);
    uint32_t bRow[2];
    #pragma unroll
    for (int bi = 0; bi < 2; bi++)
        bRow[bi] = (uint32_t)((wn * 32 + bi * 16 + rowB) * 128);

    const int nK = K >> 6;

    LOAD_STAGE(0, 0);
    cp_commit();
    LOAD_STAGE(1, 64);
    cp_commit();

    for (int ks = 0; ks < nK; ks++) {
        if (ks + 1 < nK) cp_wait<1>(); else cp_wait<0>();
        __syncthreads();

        if (ks + 2 < nK) {
            LOAD_STAGE((ks + 2) % 3, (ks + 2) * 64);
            cp_commit();
        }

        uint32_t sb  = sm0 + (uint32_t)(ks % 3) * GSM_STAGE;
        uint32_t sAh = sb, sAl = sb + GSM_TILE, sBh = sb + 2 * GSM_TILE, sBl = sb + 3 * GSM_TILE;

        #pragma unroll
        for (int kk = 0; kk < 4; kk++) {
            uint32_t kb = kk * 32;
            uint32_t aOff = (kb + aCol) ^ aX;
            uint32_t bOff = (kb + bCol) ^ bX;

            uint32_t ah[2][4], al[2][4], bh[2][4], bl[2][4];
            #pragma unroll
            for (int mi = 0; mi < 2; mi++) {
                ldsm4(ah[mi][0], ah[mi][1], ah[mi][2], ah[mi][3], sAh + aRow[mi] + aOff);
                ldsm4(al[mi][0], al[mi][1], al[mi][2], al[mi][3], sAl + aRow[mi] + aOff);
            }
            #pragma unroll
            for (int bi = 0; bi < 2; bi++) {
                ldsm4(bh[bi][0], bh[bi][1], bh[bi][2], bh[bi][3], sBh + bRow[bi] + bOff);
                ldsm4(bl[bi][0], bl[bi][1], bl[bi][2], bl[bi][3], sBl + bRow[bi] + bOff);
            }
            #pragma unroll
            for (int mi = 0; mi < 2; mi++)
                #pragma unroll
                for (int nj = 0; nj < 4; nj++) {
                    int bi = nj >> 1, hf = nj & 1;
                    float* d = acc[mi][nj];
                    mma_bf16(d, ah[mi], bh[bi][hf * 2], bh[bi][hf * 2 + 1]);
                    mma_bf16(d, ah[mi], bl[bi][hf * 2], bl[bi][hf * 2 + 1]);
                    mma_bf16(d, al[mi], bh[bi][hf * 2], bh[bi][hf * 2 + 1]);
                }
        }
        __syncthreads();
    }

    // epilogue
    const int g = lane >> 2, i2 = (lane & 3) * 2;
    #pragma unroll
    for (int mi = 0; mi < 2; mi++) {
        int r0 = bm * 128 + wm * 32 + mi * 16 + g;
        #pragma unroll
        for (int nj = 0; nj < 4; nj++) {
            int c = bn * 128 + wn * 32 + nj * 8 + i2;
            *(float2*)(C + (size_t)r0 * N + c)       = make_float2(acc[mi][nj][0], acc[mi][nj][1]);
            *(float2*)(C + (size_t)(r0 + 8) * N + c) = make_float2(acc[mi][nj][2], acc[mi][nj][3]);
        }
    }
}

// ---------------------------------------------------------------------------
// RoPE + per-head justnorm + sqk scale. One warp per (b,h,t) token.
// ---------------------------------------------------------------------------
__global__ __launch_bounds__(128) void rope_kernel(const float* __restrict__ sqk)
{
    int w = blockIdx.x * 4 + (threadIdx.x >> 5);
    int lane = threadIdx.x & 31;
    int t = w & (Tz - 1);
    int h = (w >> 11) & (Hz - 1);
    int b = w >> 15;

    const float* base = g_qkv_raw + (size_t)(b * Tz + t) * (3 * Hz * DI) + h * (3 * DI);

    float invf = expf(-0.28782313662425575f * (float)lane);
    float fr = (float)t * invf;
    float s, c;
    sincosf(fr, &s, &c);

    float q0 = base[lane],      q1 = base[lane + 32];
    float k0 = base[64 + lane], k1 = base[96 + lane];
    float qr0 = q0 * c - q1 * s, qr1 = q1 * c + q0 * s;
    float kr0 = k0 * c - k1 * s, kr1 = k1 * c + k0 * s;

    float nq = qr0 * qr0 + qr1 * qr1;
    float nk = kr0 * kr0 + kr1 * kr1;
    #pragma unroll
    for (int o = 16; o; o >>= 1) {
        nq += __shfl_xor_sync(0xffffffffu, nq, o);
        nk += __shfl_xor_sync(0xffffffffu, nk, o);
    }
    float rq = rsqrtf(nq), rk = rsqrtf(nk);
    float s0 = sqk[h * DI + lane] * SQRT_DM;
    float s1 = sqk[h * DI + lane + 32] * SQRT_DM;

    size_t orow = ((size_t)(b * Hz + h) * Tz + t) * DI;
    g_Q[orow + lane]      = qr0 * rq * s0;
    g_Q[orow + lane + 32] = qr1 * rq * s1;
    g_K[orow + lane]      = kr0 * rk * s0;
    g_K[orow + lane + 32] = kr1 * rk * s1;
    g_V[orow + lane]      = base[128 + lane];
    g_V[orow + lane + 32] = base[160 + lane];
}

// ---------------------------------------------------------------------------
// Causal flash attention, fp32, 64x64 tiles, online softmax.
// Epilogue writes bf16 hi/lo [B, T, H*di] for the W_O tensor-core GEMM.
// ---------------------------------------------------------------------------
#define SP 65
#define ATTN_SMEM_BYTES ((4 * 64 * SP + 3 * 64) * 4)

__global__ __launch_bounds__(256) void attn_kernel()
{
    extern __shared__ float sm[];
    float* Qs = sm;
    float* Ks = Qs + 64 * SP;
    float* Vs = Ks + 64 * SP;
    float* Ss = Vs + 64 * SP;
    float* mrow = Ss + 64 * SP;
    float* lrow = mrow + 64;
    float* arow = lrow + 64;

    const int qt = blockIdx.x, h = blockIdx.y, b = blockIdx.z;
    const int tid = threadIdx.x;
    const int tx = tid & 15, ty = tid >> 4;

    const size_t bh = ((size_t)b * Hz + h) * Tz;
    const float* Qg = g_Q + (bh + (size_t)qt * 64) * DI;

    for (int idx = tid; idx < 4096; idx += 256)
        Qs[(idx >> 6) * SP + (idx & 63)] = Qg[idx];
    if (tid < 64) { mrow[tid] = -3.0e38f; lrow[tid] = 0.f; }

    float acc[4][4];
    #pragma unroll
    for (int i = 0; i < 4; i++)
        #pragma unroll
        for (int j = 0; j < 4; j++) acc[i][j] = 0.f;

    for (int jt = 0; jt <= qt; jt++) {
        __syncthreads();
        const float* Kg = g_K + (bh + (size_t)jt * 64) * DI;
        const float* Vg = g_V + (bh + (size_t)jt * 64) * DI;
        for (int idx = tid; idx < 4096; idx += 256) {
            int r = idx >> 6, cc = idx & 63;
            Ks[r * SP + cc] = Kg[idx];
            Vs[r * SP + cc] = Vg[idx];
        }
        __syncthreads();

        float sv[4][4];
        #pragma unroll
        for (int i = 0; i < 4; i++)
            #pragma unroll
            for (int j = 0; j < 4; j++) sv[i][j] = 0.f;

        #pragma unroll 8
        for (int d = 0; d < 64; d++) {
            float a[4], bb[4];
            #pragma unroll
            for (int i = 0; i < 4; i++) a[i] = Qs[(ty * 4 + i) * SP + d];
            #pragma unroll
            for (int j = 0; j < 4; j++) bb[j] = Ks[(tx * 4 + j) * SP + d];
            #pragma unroll
            for (int i = 0; i < 4; i++)
                #pragma unroll
                for (int j = 0; j < 4; j++)
                    sv[i][j] += a[i] * bb[j];
        }

        const bool diag = (jt == qt);
        #pragma unroll
        for (int i = 0; i < 4; i++)
            #pragma unroll
            for (int j = 0; j < 4; j++) {
                float v = sv[i][j] * SQRT_DM;
                if (diag && (tx * 4 + j) > (ty * 4 + i)) v = -1.0e30f;
                Ss[(ty * 4 + i) * SP + tx * 4 + j] = v;
            }
        __syncthreads();

        if (tid < 64) {
            float* srow = Ss + tid * SP;
            float m_old = mrow[tid];
            float mx = m_old;
            for (int cc = 0; cc < 64; cc++) mx = fmaxf(mx, srow[cc]);
            float alpha = expf(m_old - mx);
            float sum = 0.f;
            for (int cc = 0; cc < 64; cc++) {
                float p = expf(srow[cc] - mx);
                srow[cc] = p;
                sum += p;
            }
            lrow[tid] = lrow[tid] * alpha + sum;
            mrow[tid] = mx;
            arow[tid] = alpha;
        }
        __syncthreads();

        #pragma unroll
        for (int i = 0; i < 4; i++) {
            float al = arow[ty * 4 + i];
            #pragma unroll
            for (int j = 0; j < 4; j++) acc[i][j] *= al;
        }
        #pragma unroll 8
        for (int cc = 0; cc < 64; cc++) {
            float p[4], v[4];
            #pragma unroll
            for (int i = 0; i < 4; i++) p[i] = Ss[(ty * 4 + i) * SP + cc];
            #pragma unroll
            for (int j = 0; j < 4; j++) v[j] = Vs[cc * SP + tx * 4 + j];
            #pragma unroll
            for (int i = 0; i < 4; i++)
                #pragma unroll
                for (int j = 0; j < 4; j++)
                    acc[i][j] += p[i] * v[j];
        }
    }
    __syncthreads();

    #pragma unroll
    for (int i = 0; i < 4; i++) {
        int r = ty * 4 + i;
        float inv = 1.0f / lrow[r];
        size_t orow = ((size_t)b * Tz + (size_t)qt * 64 + r) * DM + h * DI + tx * 4;
        #pragma unroll
        for (int j = 0; j < 4; j++) {
            float v = acc[i][j] * inv;
            bf16 hh = __float2bfloat16(v);
            g_attn_h[orow + j] = hh;
            g_attn_l[orow + j] = __float2bfloat16(v - __bfloat162float(hh));
        }
    }
}

// ---------------------------------------------------------------------------
// block-wide all-reduce sum (256 threads)
// ---------------------------------------------------------------------------
__device__ __forceinline__ float blockAllReduceSum(float v)
{
    __shared__ float red[8];
    int lane = threadIdx.x & 31, w = threadIdx.x >> 5;
    #pragma unroll
    for (int o = 16; o; o >>= 1) v += __shfl_xor_sync(0xffffffffu, v, o);
    if (lane == 0) red[w] = v;
    __syncthreads();
    float s = 0.f;
    #pragma unroll
    for (int i = 0; i < 8; i++) s += red[i];
    __syncthreads();
    return s;
}

// ---------------------------------------------------------------------------
// nGPT residual lerp + norms; optional fused bf16 hi/lo output.
// ---------------------------------------------------------------------------
__global__ __launch_bounds__(256) void resnorm_kernel(
    const float* __restrict__ X, const float* __restrict__ Tm,
    const float* __restrict__ alpha, float coef, float* __restrict__ out,
    bf16* __restrict__ oh, bf16* __restrict__ ol)
{
    int row = blockIdx.x, tid = threadIdx.x;
    const float* x = X  + (size_t)row * DM;
    const float* t = Tm + (size_t)row * DM;

    float xv[4], tv[4];
    float sx = 0.f, st = 0.f;
    #pragma unroll
    for (int i = 0; i < 4; i++) {
        int j = tid + i * 256;
        xv[i] = x[j]; tv[i] = t[j];
        sx += xv[i] * xv[i]; st += tv[i] * tv[i];
    }
    sx = blockAllReduceSum(sx);
    st = blockAllReduceSum(st);
    float rx = rsqrtf(sx), rt = rsqrtf(st);

    float yv[4];
    float sy = 0.f;
    #pragma unroll
    for (int i = 0; i < 4; i++) {
        int j = tid + i * 256;
        float a  = xv[i] * rx;
        float bn = tv[i] * rt;
        float lr = fabsf(alpha[j] * coef);
        yv[i] = a + lr * (bn - a);
        sy += yv[i] * yv[i];
    }
    sy = blockAllReduceSum(sy);
    float ry = rsqrtf(sy);

    float* o = out + (size_t)row * DM;
    #pragma unroll
    for (int i = 0; i < 4; i++) {
        int j = tid + i * 256;
        float v = yv[i] * ry;
        o[j] = v;
        if (oh) {
            bf16 hh = __float2bfloat16(v);
            oh[(size_t)row * DM + j] = hh;
            ol[(size_t)row * DM + j] = __float2bfloat16(v - __bfloat162float(hh));
        }
    }
}

// ---------------------------------------------------------------------------
// MLP activation: tn = justnorm(suv*32 * uv) over 8192; res = u * silu(v)
// Writes bf16 hi/lo only (consumed by Wv tensor-core GEMM).
// ---------------------------------------------------------------------------
__global__ __launch_bounds__(256) void mlp_act_kernel(const float* __restrict__ suv)
{
    int row = blockIdx.x, tid = threadIdx.x;
    const float* uv = g_uv + (size_t)row * (8 * DM);

    float s = 0.f;
    for (int j = tid; j < 8 * DM; j += 256) {
        float v = suv[j] * SQRT_DM * uv[j];
        s += v * v;
    }
    s = blockAllReduceSum(s);
    float rn = rsqrtf(s);

    bf16* rh = g_res_h + (size_t)row * (4 * DM);
    bf16* rl = g_res_l + (size_t)row * (4 * DM);
    for (int j = tid; j < 4 * DM; j += 256) {
        float u = suv[j] * SQRT_DM * uv[j] * rn;
        float v = suv[j + 4 * DM] * SQRT_DM * uv[j + 4 * DM] * rn;
        float r = u * v / (1.0f + expf(-v));
        bf16 hh = __float2bfloat16(r);
        rh[j] = hh;
        rl[j] = __float2bfloat16(r - __bfloat162float(hh));
    }
}

// ---------------------------------------------------------------------------
// Host launch
// ---------------------------------------------------------------------------
extern "C" void kernel_launch(void* const* d_in, const int* in_sizes, int n_in,
                              void* d_out, int out_size)
{
    const float* x          = (const float*)d_in[0];
    const float* qkv        = (const float*)d_in[1];
    const float* sqk        = (const float*)d_in[2];
    const float* W_O        = (const float*)d_in[3];
    const float* Wu         = (const float*)d_in[4];
    const float* Wv         = (const float*)d_in[5];
    const float* attn_alpha = (const float*)d_in[6];
    const float* mlp_alpha  = (const float*)d_in[7];
    const float* suv        = (const float*)d_in[8];
    float* out = (float*)d_out;

    float *qkv_raw, *tb, *x1b, *uvb;
    cudaGetSymbolAddress((void**)&qkv_raw, g_qkv_raw);
    cudaGetSymbolAddress((void**)&tb,      g_t);
    cudaGetSymbolAddress((void**)&x1b,     g_x1);
    cudaGetSymbolAddress((void**)&uvb,     g_uv);

    bf16 *xh, *xl, *qwh, *qwl, *woh, *wol, *wuh, *wul, *wvh, *wvl;
    bf16 *ath, *atl, *x1h, *x1l, *rsh, *rsl;
    cudaGetSymbolAddress((void**)&xh,  g_x_h);   cudaGetSymbolAddress((void**)&xl,  g_x_l);
    cudaGetSymbolAddress((void**)&qwh, g_qkvw_h);cudaGetSymbolAddress((void**)&qwl, g_qkvw_l);
    cudaGetSymbolAddress((void**)&woh, g_Wo_h);  cudaGetSymbolAddress((void**)&wol, g_Wo_l);
    cudaGetSymbolAddress((void**)&wuh, g_Wu_h);  cudaGetSymbolAddress((void**)&wul, g_Wu_l);
    cudaGetSymbolAddress((void**)&wvh, g_Wv_h);  cudaGetSymbolAddress((void**)&wvl, g_Wv_l);
    cudaGetSymbolAddress((void**)&ath, g_attn_h);cudaGetSymbolAddress((void**)&atl, g_attn_l);
    cudaGetSymbolAddress((void**)&x1h, g_x1_h);  cudaGetSymbolAddress((void**)&x1l, g_x1_l);
    cudaGetSymbolAddress((void**)&rsh, g_res_h); cudaGetSymbolAddress((void**)&rsl, g_res_l);

    cudaFuncSetAttribute(attn_kernel, cudaFuncAttributeMaxDynamicSharedMemorySize,
                         ATTN_SMEM_BYTES);
    cudaFuncSetAttribute(gemm_bf16x3, cudaFuncAttributeMaxDynamicSharedMemorySize,
                         GSM_TOTAL);

    // 0) hi/lo conversions (input x + weights)
    convert_hl<<<(ROWS * DM) / 256, 256>>>(x, xh, xl, ROWS * DM);
    convert_hl<<<(3 * DM * DM) / 256, 256>>>(qkv, qwh, qwl, 3 * DM * DM);
    convert_hl<<<(DM * DM) / 256, 256>>>(W_O, woh, wol, DM * DM);
    convert_hl<<<(8 * DM * DM) / 256, 256>>>(Wu, wuh, wul, 8 * DM * DM);
    convert_hl<<<(DM * 4 * DM) / 256, 256>>>(Wv, wvh, wvl, DM * 4 * DM);

    // 1) QKV projection: [8192,3072] = x @ qkv^T
    gemm_bf16x3<<<dim3(3 * DM / 128, ROWS / 128), 512, GSM_TOTAL>>>(
        xh, xl, qwh, qwl, qkv_raw, ROWS, 3 * DM, DM);

    // 2) RoPE + justnorm + sqk scale
    rope_kernel<<<(Bz * Hz * Tz) / 4, 128>>>(sqk);

    // 3) causal attention (writes bf16 hi/lo attn out)
    attn_kernel<<<dim3(Tz / 64, Hz, Bz), 256, ATTN_SMEM_BYTES>>>();

    // 4) W_O projection
    gemm_bf16x3<<<dim3(DM / 128, ROWS / 128), 512, GSM_TOTAL>>>(
        ath, atl, woh, wol, tb, ROWS, DM, DM);

    // 5) residual lerp #1 (coef = 0.05*sqrt(dm) = 1.6), fused x1 hi/lo
    resnorm_kernel<<<ROWS, 256>>>(x, tb, attn_alpha, 1.6f, x1b, x1h, x1l);

    // 6) Wu: uv = x1 @ Wu^T  [8192,8192]
    gemm_bf16x3<<<dim3(8 * DM / 128, ROWS / 128), 512, GSM_TOTAL>>>(
        x1h, x1l, wuh, wul, uvb, ROWS, 8 * DM, DM);

    // 7) scale + full-vector justnorm + SwiGLU (writes bf16 hi/lo res)
    mlp_act_kernel<<<ROWS, 256>>>(suv);

    // 8) Wv: t = res @ Wv^T   (K = 4096)
    gemm_bf16x3<<<dim3(DM / 128, ROWS / 128), 512, GSM_TOTAL>>>(
        rsh, rsl, wvh, wvl, tb, ROWS, DM, 4 * DM);

    // 9) residual lerp #2 (coef = 0.05) -> final output
    resnorm_kernel<<<ROWS, 256>>>(x1b, tb, mlp_alpha, 0.05f, out, (bf16*)0, (bf16*)0);
}

// round 6
// speedup vs baseline: 1.5118x; 1.5118x over previous
#include <cuda_runtime.h>
#include <cuda_bf16.h>
#include <math.h>
#include <stdint.h>

// Problem constants
#define Bz 4
#define Tz 2048
#define DM 1024
#define Hz 16
#define DI 64
#define ROWS (Bz*Tz)            // 8192
#define SQRT_DM 32.0f

// ---------------------------------------------------------------------------
// Scratch (static device globals; no allocations allowed)
// ---------------------------------------------------------------------------
__device__ float g_qkv_raw[(size_t)ROWS * 3 * DM];        // [8192, 3072]
__device__ float g_Q[(size_t)Bz * Hz * Tz * DI];          // [B,H,T,di]
__device__ float g_K[(size_t)Bz * Hz * Tz * DI];
__device__ float g_V[(size_t)Bz * Hz * Tz * DI];
__device__ float g_attn[(size_t)ROWS * DM];
__device__ float g_t[(size_t)ROWS * DM];
__device__ float g_x1[(size_t)ROWS * DM];
__device__ float g_uv[(size_t)ROWS * 8 * DM];             // [8192,8192]
__device__ float g_res[(size_t)ROWS * 4 * DM];            // [8192,4096]

// int8 hi/lo quantized operands + per-row scales
__device__ int8_t g_x_h[(size_t)ROWS * DM],      g_x_l[(size_t)ROWS * DM];
__device__ int8_t g_qw_h[(size_t)3 * DM * DM],   g_qw_l[(size_t)3 * DM * DM];
__device__ int8_t g_wo_h[(size_t)DM * DM],       g_wo_l[(size_t)DM * DM];
__device__ int8_t g_wu_h[(size_t)8 * DM * DM],   g_wu_l[(size_t)8 * DM * DM];
__device__ int8_t g_wv_h[(size_t)DM * 4 * DM],   g_wv_l[(size_t)DM * 4 * DM];
__device__ int8_t g_at_h[(size_t)ROWS * DM],     g_at_l[(size_t)ROWS * DM];
__device__ int8_t g_x1_h[(size_t)ROWS * DM],     g_x1_l[(size_t)ROWS * DM];
__device__ int8_t g_rs_h[(size_t)ROWS * 4 * DM], g_rs_l[(size_t)ROWS * 4 * DM];

__device__ float g_sc_x[ROWS], g_sc_qw[3 * DM], g_sc_wo[DM], g_sc_wu[8 * DM];
__device__ float g_sc_wv[DM],  g_sc_at[ROWS],   g_sc_x1[ROWS], g_sc_rs[ROWS];

// ---------------------------------------------------------------------------
// block-wide reductions (256 threads)
// ---------------------------------------------------------------------------
__device__ __forceinline__ float blockAllReduceSum(float v)
{
    __shared__ float red[8];
    int lane = threadIdx.x & 31, w = threadIdx.x >> 5;
    #pragma unroll
    for (int o = 16; o; o >>= 1) v += __shfl_xor_sync(0xffffffffu, v, o);
    if (lane == 0) red[w] = v;
    __syncthreads();
    float s = 0.f;
    #pragma unroll
    for (int i = 0; i < 8; i++) s += red[i];
    __syncthreads();
    return s;
}
__device__ __forceinline__ float blockAllReduceMax(float v)
{
    __shared__ float redm[8];
    int lane = threadIdx.x & 31, w = threadIdx.x >> 5;
    #pragma unroll
    for (int o = 16; o; o >>= 1) v = fmaxf(v, __shfl_xor_sync(0xffffffffu, v, o));
    if (lane == 0) redm[w] = v;
    __syncthreads();
    float s = -1.f;
    #pragma unroll
    for (int i = 0; i < 8; i++) s = fmaxf(s, redm[i]);
    __syncthreads();
    return s;
}

// ---------------------------------------------------------------------------
// Row-wise int16-split quantization: v = round(x/rowmax*32512), v = 256*hi+lo
// One block (256 thr) per row.
// ---------------------------------------------------------------------------
__global__ __launch_bounds__(256) void quant_rows(
    const float* __restrict__ src, int8_t* __restrict__ hi, int8_t* __restrict__ lo,
    float* __restrict__ scale, int K)
{
    int row = blockIdx.x, tid = threadIdx.x;
    const float* x = src + (size_t)row * K;

    float mx = 0.f;
    for (int j = tid; j < K; j += 256) mx = fmaxf(mx, fabsf(x[j]));
    mx = blockAllReduceMax(mx);

    float inv = (mx > 0.f) ? 32512.0f / mx : 0.f;
    if (tid == 0) scale[row] = (mx > 0.f) ? mx / 32512.0f : 0.f;

    int8_t* hrow = hi + (size_t)row * K;
    int8_t* lrow = lo + (size_t)row * K;
    for (int j = tid; j < K; j += 256) {
        int v = __float2int_rn(x[j] * inv);
        v = max(-32512, min(32512, v));
        int h = (v + 128) >> 8;            // floor((v+128)/256) in [-127,127]
        int l = v - (h << 8);              // in [-128,127]
        hrow[j] = (int8_t)h;
        lrow[j] = (int8_t)l;
    }
}

// ---------------------------------------------------------------------------
// int8x3 tensor-core GEMM:  C[M,N] = A[M,K] @ B[N,K]^T
//   P1 += Ah*Bh ; P2 += Ah*Bl + Al*Bh ; C = sA*sB*(65536*P1 + 256*P2)
// BM=BN=128, BK=128 (int8), 256 threads (8 warps 2x4), warp tile 64x32.
// SW128 swizzled smem, cp.async double buffered. (addressing identical to the
// validated bf16 kernel: s8 k32 fragments == b16 k16 fragments bytewise)
// ---------------------------------------------------------------------------
#define SWZ(off) ((off) ^ (((off) >> 3) & 0x70))
#define GSM_TILE  16384
#define GSM_STAGE 65536
#define GSM_TOTAL 131072

__device__ __forceinline__ void cpasync16(uint32_t dst, const void* src) {
    asm volatile("cp.async.cg.shared.global [%0], [%1], 16;\n" :: "r"(dst), "l"(src));
}
__device__ __forceinline__ void cp_commit() { asm volatile("cp.async.commit_group;\n"); }
template<int N> __device__ __forceinline__ void cp_wait() {
    asm volatile("cp.async.wait_group %0;\n" :: "n"(N));
}
__device__ __forceinline__ void ldsm4(uint32_t& r0, uint32_t& r1, uint32_t& r2, uint32_t& r3, uint32_t a) {
    asm volatile("ldmatrix.sync.aligned.m8n8.x4.shared.b16 {%0,%1,%2,%3}, [%4];"
                 : "=r"(r0), "=r"(r1), "=r"(r2), "=r"(r3) : "r"(a));
}
__device__ __forceinline__ void mma_s8(int* d, const uint32_t* a, uint32_t b0, uint32_t b1) {
    asm volatile("mma.sync.aligned.m16n8k32.row.col.s32.s8.s8.s32 "
                 "{%0,%1,%2,%3}, {%4,%5,%6,%7}, {%8,%9}, {%0,%1,%2,%3};"
                 : "+r"(d[0]), "+r"(d[1]), "+r"(d[2]), "+r"(d[3])
                 : "r"(a[0]), "r"(a[1]), "r"(a[2]), "r"(a[3]), "r"(b0), "r"(b1));
}

#define LOAD_STAGE(sbuf, k0)                                                   \
    do {                                                                       \
        uint32_t _sb = sm0 + (uint32_t)(sbuf) * GSM_STAGE;                     \
        _Pragma("unroll")                                                      \
        for (int _t = 0; _t < 4; _t++) {                                       \
            const int8_t* _g = tp[_t] + (k0);                                  \
            uint32_t _sbt = _sb + _t * GSM_TILE;                               \
            _Pragma("unroll")                                                  \
            for (int _u = 0; _u < 4; _u++) {                                   \
                int _r = lr + _u * 32;                                         \
                uint32_t _off = (uint32_t)(_r * 128 + lc * 16);                \
                cpasync16(_sbt + SWZ(_off), _g + (size_t)_r * K + lc * 16);    \
            }                                                                  \
        }                                                                      \
    } while (0)

__global__ __launch_bounds__(256, 1) void gemm_s8x3(
    const int8_t* __restrict__ Ah, const int8_t* __restrict__ Al,
    const int8_t* __restrict__ Bh, const int8_t* __restrict__ Bl,
    const float* __restrict__ sA, const float* __restrict__ sB,
    float* __restrict__ C, int M, int N, int K)
{
    extern __shared__ __align__(1024) unsigned char smraw[];
    uint32_t sm0 = (uint32_t)__cvta_generic_to_shared(smraw);

    const int tid = threadIdx.x, lane = tid & 31, wid = tid >> 5;
    const int wm = wid >> 2, wn = wid & 3;
    const int bn = blockIdx.x, bm = blockIdx.y;

    const size_t aoff = (size_t)bm * 128 * K;
    const size_t boff = (size_t)bn * 128 * K;
    const int8_t* tp[4] = { Ah + aoff, Al + aoff, Bh + boff, Bl + boff };

    const int lr = tid >> 3;     // 0..31
    const int lc = tid & 7;      // 16B chunk

    int p1[4][4][4], p2[4][4][4];
    #pragma unroll
    for (int a = 0; a < 4; a++)
        #pragma unroll
        for (int b = 0; b < 4; b++)
            #pragma unroll
            for (int c = 0; c < 4; c++) { p1[a][b][c] = 0; p2[a][b][c] = 0; }

    // ldmatrix per-lane offsets (b16 view: 64 b16 per 128B row)
    const int rowA = lane & 15;
    const uint32_t aCol = (uint32_t)((lane >> 4) * 16);
    const uint32_t aX   = (uint32_t)((rowA & 7) << 4);
    uint32_t aRow[4];
    #pragma unroll
    for (int mi = 0; mi < 4; mi++)
        aRow[mi] = (uint32_t)((wm * 64 + mi * 16 + rowA) * 128);

    const int rowB = ((lane >> 4) << 3) | (lane & 7);
    const uint32_t bCol = (uint32_t)(((lane >> 3) & 1) * 16);
    const uint32_t bX   = (uint32_t)((rowB & 7) << 4);
    uint32_t bRow[2];
    #pragma unroll
    for (int bi = 0; bi < 2; bi++)
        bRow[bi] = (uint32_t)((wn * 32 + bi * 16 + rowB) * 128);

    const int nK = K >> 7;       // stages of 128 int8

    LOAD_STAGE(0, 0);
    cp_commit();

    for (int ks = 0; ks < nK; ks++) {
        if (ks + 1 < nK) {
            LOAD_STAGE((ks + 1) & 1, (ks + 1) * 128);
            cp_commit();
            cp_wait<1>();
        } else {
            cp_wait<0>();
        }
        __syncthreads();

        uint32_t sb  = sm0 + (uint32_t)(ks & 1) * GSM_STAGE;
        uint32_t sAh = sb, sAl = sb + GSM_TILE, sBh = sb + 2 * GSM_TILE, sBl = sb + 3 * GSM_TILE;

        #pragma unroll
        for (int kk = 0; kk < 4; kk++) {      // 4 x k32
            uint32_t kb = kk * 32;            // 32 bytes per k32 step
            uint32_t aOff = (kb + aCol) ^ aX;
            uint32_t bOff = (kb + bCol) ^ bX;

            uint32_t ah[4][4], al[4][4], bh[2][4], bl[2][4];
            #pragma unroll
            for (int mi = 0; mi < 4; mi++) {
                ldsm4(ah[mi][0], ah[mi][1], ah[mi][2], ah[mi][3], sAh + aRow[mi] + aOff);
                ldsm4(al[mi][0], al[mi][1], al[mi][2], al[mi][3], sAl + aRow[mi] + aOff);
            }
            #pragma unroll
            for (int bi = 0; bi < 2; bi++) {
                ldsm4(bh[bi][0], bh[bi][1], bh[bi][2], bh[bi][3], sBh + bRow[bi] + bOff);
                ldsm4(bl[bi][0], bl[bi][1], bl[bi][2], bl[bi][3], sBl + bRow[bi] + bOff);
            }
            #pragma unroll
            for (int mi = 0; mi < 4; mi++)
                #pragma unroll
                for (int nj = 0; nj < 4; nj++) {
                    int bi = nj >> 1, hf = nj & 1;
                    mma_s8(p1[mi][nj], ah[mi], bh[bi][hf * 2], bh[bi][hf * 2 + 1]);
                    mma_s8(p2[mi][nj], ah[mi], bl[bi][hf * 2], bl[bi][hf * 2 + 1]);
                    mma_s8(p2[mi][nj], al[mi], bh[bi][hf * 2], bh[bi][hf * 2 + 1]);
                }
        }
        __syncthreads();
    }

    // epilogue: C = sA[r]*sB[c]*(65536*P1 + 256*P2)
    const int g = lane >> 2, i2 = (lane & 3) * 2;
    #pragma unroll
    for (int mi = 0; mi < 4; mi++) {
        int r0 = bm * 128 + wm * 64 + mi * 16 + g;
        float sa0 = sA[r0], sa1 = sA[r0 + 8];
        #pragma unroll
        for (int nj = 0; nj < 4; nj++) {
            int c = bn * 128 + wn * 32 + nj * 8 + i2;
            float sb0 = sB[c], sb1 = sB[c + 1];
            int* q1 = p1[mi][nj];
            int* q2 = p2[mi][nj];
            float v0 = sa0 * sb0 * (65536.f * (float)q1[0] + 256.f * (float)q2[0]);
            float v1 = sa0 * sb1 * (65536.f * (float)q1[1] + 256.f * (float)q2[1]);
            float v2 = sa1 * sb0 * (65536.f * (float)q1[2] + 256.f * (float)q2[2]);
            float v3 = sa1 * sb1 * (65536.f * (float)q1[3] + 256.f * (float)q2[3]);
            *(float2*)(C + (size_t)r0 * N + c)       = make_float2(v0, v1);
            *(float2*)(C + (size_t)(r0 + 8) * N + c) = make_float2(v2, v3);
        }
    }
}

// ---------------------------------------------------------------------------
// RoPE + per-head justnorm + sqk scale. One warp per (b,h,t) token.
// ---------------------------------------------------------------------------
__global__ __launch_bounds__(128) void rope_kernel(const float* __restrict__ sqk)
{
    int w = blockIdx.x * 4 + (threadIdx.x >> 5);
    int lane = threadIdx.x & 31;
    int t = w & (Tz - 1);
    int h = (w >> 11) & (Hz - 1);
    int b = w >> 15;

    const float* base = g_qkv_raw + (size_t)(b * Tz + t) * (3 * Hz * DI) + h * (3 * DI);

    float invf = expf(-0.28782313662425575f * (float)lane);
    float fr = (float)t * invf;
    float s, c;
    sincosf(fr, &s, &c);

    float q0 = base[lane],      q1 = base[lane + 32];
    float k0 = base[64 + lane], k1 = base[96 + lane];
    float qr0 = q0 * c - q1 * s, qr1 = q1 * c + q0 * s;
    float kr0 = k0 * c - k1 * s, kr1 = k1 * c + k0 * s;

    float nq = qr0 * qr0 + qr1 * qr1;
    float nk = kr0 * kr0 + kr1 * kr1;
    #pragma unroll
    for (int o = 16; o; o >>= 1) {
        nq += __shfl_xor_sync(0xffffffffu, nq, o);
        nk += __shfl_xor_sync(0xffffffffu, nk, o);
    }
    float rq = rsqrtf(nq), rk = rsqrtf(nk);
    float s0 = sqk[h * DI + lane] * SQRT_DM;
    float s1 = sqk[h * DI + lane + 32] * SQRT_DM;

    size_t orow = ((size_t)(b * Hz + h) * Tz + t) * DI;
    g_Q[orow + lane]      = qr0 * rq * s0;
    g_Q[orow + lane + 32] = qr1 * rq * s1;
    g_K[orow + lane]      = kr0 * rk * s0;
    g_K[orow + lane + 32] = kr1 * rk * s1;
    g_V[orow + lane]      = base[128 + lane];
    g_V[orow + lane + 32] = base[160 + lane];
}

// ---------------------------------------------------------------------------
// Causal flash attention, fp32, 64x64 tiles, online softmax.
// Writes fp32 g_attn in [B, T, H*di] layout.
// ---------------------------------------------------------------------------
#define SP 65
#define ATTN_SMEM_BYTES ((4 * 64 * SP + 3 * 64) * 4)

__global__ __launch_bounds__(256) void attn_kernel()
{
    extern __shared__ float sm[];
    float* Qs = sm;
    float* Ks = Qs + 64 * SP;
    float* Vs = Ks + 64 * SP;
    float* Ss = Vs + 64 * SP;
    float* mrow = Ss + 64 * SP;
    float* lrow = mrow + 64;
    float* arow = lrow + 64;

    const int qt = blockIdx.x, h = blockIdx.y, b = blockIdx.z;
    const int tid = threadIdx.x;
    const int tx = tid & 15, ty = tid >> 4;

    const size_t bh = ((size_t)b * Hz + h) * Tz;
    const float* Qg = g_Q + (bh + (size_t)qt * 64) * DI;

    for (int idx = tid; idx < 4096; idx += 256)
        Qs[(idx >> 6) * SP + (idx & 63)] = Qg[idx];
    if (tid < 64) { mrow[tid] = -3.0e38f; lrow[tid] = 0.f; }

    float acc[4][4];
    #pragma unroll
    for (int i = 0; i < 4; i++)
        #pragma unroll
        for (int j = 0; j < 4; j++) acc[i][j] = 0.f;

    for (int jt = 0; jt <= qt; jt++) {
        __syncthreads();
        const float* Kg = g_K + (bh + (size_t)jt * 64) * DI;
        const float* Vg = g_V + (bh + (size_t)jt * 64) * DI;
        for (int idx = tid; idx < 4096; idx += 256) {
            int r = idx >> 6, cc = idx & 63;
            Ks[r * SP + cc] = Kg[idx];
            Vs[r * SP + cc] = Vg[idx];
        }
        __syncthreads();

        float sv[4][4];
        #pragma unroll
        for (int i = 0; i < 4; i++)
            #pragma unroll
            for (int j = 0; j < 4; j++) sv[i][j] = 0.f;

        #pragma unroll 8
        for (int d = 0; d < 64; d++) {
            float a[4], bb[4];
            #pragma unroll
            for (int i = 0; i < 4; i++) a[i] = Qs[(ty * 4 + i) * SP + d];
            #pragma unroll
            for (int j = 0; j < 4; j++) bb[j] = Ks[(tx * 4 + j) * SP + d];
            #pragma unroll
            for (int i = 0; i < 4; i++)
                #pragma unroll
                for (int j = 0; j < 4; j++)
                    sv[i][j] += a[i] * bb[j];
        }

        const bool diag = (jt == qt);
        #pragma unroll
        for (int i = 0; i < 4; i++)
            #pragma unroll
            for (int j = 0; j < 4; j++) {
                float v = sv[i][j] * SQRT_DM;
                if (diag && (tx * 4 + j) > (ty * 4 + i)) v = -1.0e30f;
                Ss[(ty * 4 + i) * SP + tx * 4 + j] = v;
            }
        __syncthreads();

        if (tid < 64) {
            float* srow = Ss + tid * SP;
            float m_old = mrow[tid];
            float mx = m_old;
            for (int cc = 0; cc < 64; cc++) mx = fmaxf(mx, srow[cc]);
            float alpha = expf(m_old - mx);
            float sum = 0.f;
            for (int cc = 0; cc < 64; cc++) {
                float p = expf(srow[cc] - mx);
                srow[cc] = p;
                sum += p;
            }
            lrow[tid] = lrow[tid] * alpha + sum;
            mrow[tid] = mx;
            arow[tid] = alpha;
        }
        __syncthreads();

        #pragma unroll
        for (int i = 0; i < 4; i++) {
            float al = arow[ty * 4 + i];
            #pragma unroll
            for (int j = 0; j < 4; j++) acc[i][j] *= al;
        }
        #pragma unroll 8
        for (int cc = 0; cc < 64; cc++) {
            float p[4], v[4];
            #pragma unroll
            for (int i = 0; i < 4; i++) p[i] = Ss[(ty * 4 + i) * SP + cc];
            #pragma unroll
            for (int j = 0; j < 4; j++) v[j] = Vs[cc * SP + tx * 4 + j];
            #pragma unroll
            for (int i = 0; i < 4; i++)
                #pragma unroll
                for (int j = 0; j < 4; j++)
                    acc[i][j] += p[i] * v[j];
        }
    }
    __syncthreads();

    #pragma unroll
    for (int i = 0; i < 4; i++) {
        int r = ty * 4 + i;
        float inv = 1.0f / lrow[r];
        size_t orow = ((size_t)b * Tz + (size_t)qt * 64 + r) * DM + h * DI + tx * 4;
        #pragma unroll
        for (int j = 0; j < 4; j++)
            g_attn[orow + j] = acc[i][j] * inv;
    }
}

// ---------------------------------------------------------------------------
// nGPT residual lerp + norms
// ---------------------------------------------------------------------------
__global__ __launch_bounds__(256) void resnorm_kernel(
    const float* __restrict__ X, const float* __restrict__ Tm,
    const float* __restrict__ alpha, float coef, float* __restrict__ out)
{
    int row = blockIdx.x, tid = threadIdx.x;
    const float* x = X  + (size_t)row * DM;
    const float* t = Tm + (size_t)row * DM;

    float xv[4], tv[4];
    float sx = 0.f, st = 0.f;
    #pragma unroll
    for (int i = 0; i < 4; i++) {
        int j = tid + i * 256;
        xv[i] = x[j]; tv[i] = t[j];
        sx += xv[i] * xv[i]; st += tv[i] * tv[i];
    }
    sx = blockAllReduceSum(sx);
    st = blockAllReduceSum(st);
    float rx = rsqrtf(sx), rt = rsqrtf(st);

    float yv[4];
    float sy = 0.f;
    #pragma unroll
    for (int i = 0; i < 4; i++) {
        int j = tid + i * 256;
        float a  = xv[i] * rx;
        float bn = tv[i] * rt;
        float lr = fabsf(alpha[j] * coef);
        yv[i] = a + lr * (bn - a);
        sy += yv[i] * yv[i];
    }
    sy = blockAllReduceSum(sy);
    float ry = rsqrtf(sy);

    float* o = out + (size_t)row * DM;
    #pragma unroll
    for (int i = 0; i < 4; i++) o[tid + i * 256] = yv[i] * ry;
}

// ---------------------------------------------------------------------------
// MLP activation: tn = justnorm(suv*32 * uv) over 8192; res = u * silu(v)
// ---------------------------------------------------------------------------
__global__ __launch_bounds__(256) void mlp_act_kernel(const float* __restrict__ suv)
{
    int row = blockIdx.x, tid = threadIdx.x;
    const float* uv = g_uv + (size_t)row * (8 * DM);

    float s = 0.f;
    for (int j = tid; j < 8 * DM; j += 256) {
        float v = suv[j] * SQRT_DM * uv[j];
        s += v * v;
    }
    s = blockAllReduceSum(s);
    float rn = rsqrtf(s);

    float* r = g_res + (size_t)row * (4 * DM);
    for (int j = tid; j < 4 * DM; j += 256) {
        float u = suv[j] * SQRT_DM * uv[j] * rn;
        float v = suv[j + 4 * DM] * SQRT_DM * uv[j + 4 * DM] * rn;
        r[j] = u * v / (1.0f + expf(-v));
    }
}

// ---------------------------------------------------------------------------
// Host launch
// ---------------------------------------------------------------------------
extern "C" void kernel_launch(void* const* d_in, const int* in_sizes, int n_in,
                              void* d_out, int out_size)
{
    const float* x          = (const float*)d_in[0];
    const float* qkv        = (const float*)d_in[1];
    const float* sqk        = (const float*)d_in[2];
    const float* W_O        = (const float*)d_in[3];
    const float* Wu         = (const float*)d_in[4];
    const float* Wv         = (const float*)d_in[5];
    const float* attn_alpha = (const float*)d_in[6];
    const float* mlp_alpha  = (const float*)d_in[7];
    const float* suv        = (const float*)d_in[8];
    float* out = (float*)d_out;

    float *qkv_raw, *attnb, *tb, *x1b, *uvb, *resb;
    cudaGetSymbolAddress((void**)&qkv_raw, g_qkv_raw);
    cudaGetSymbolAddress((void**)&attnb,   g_attn);
    cudaGetSymbolAddress((void**)&tb,      g_t);
    cudaGetSymbolAddress((void**)&x1b,     g_x1);
    cudaGetSymbolAddress((void**)&uvb,     g_uv);
    cudaGetSymbolAddress((void**)&resb,    g_res);

    int8_t *xh, *xl, *qwh, *qwl, *woh, *wol, *wuh, *wul, *wvh, *wvl;
    int8_t *ath, *atl, *x1h, *x1l, *rsh, *rsl;
    float *scx, *scqw, *scwo, *scwu, *scwv, *scat, *scx1, *scrs;
    cudaGetSymbolAddress((void**)&xh,  g_x_h);  cudaGetSymbolAddress((void**)&xl,  g_x_l);
    cudaGetSymbolAddress((void**)&qwh, g_qw_h); cudaGetSymbolAddress((void**)&qwl, g_qw_l);
    cudaGetSymbolAddress((void**)&woh, g_wo_h); cudaGetSymbolAddress((void**)&wol, g_wo_l);
    cudaGetSymbolAddress((void**)&wuh, g_wu_h); cudaGetSymbolAddress((void**)&wul, g_wu_l);
    cudaGetSymbolAddress((void**)&wvh, g_wv_h); cudaGetSymbolAddress((void**)&wvl, g_wv_l);
    cudaGetSymbolAddress((void**)&ath, g_at_h); cudaGetSymbolAddress((void**)&atl, g_at_l);
    cudaGetSymbolAddress((void**)&x1h, g_x1_h); cudaGetSymbolAddress((void**)&x1l, g_x1_l);
    cudaGetSymbolAddress((void**)&rsh, g_rs_h); cudaGetSymbolAddress((void**)&rsl, g_rs_l);
    cudaGetSymbolAddress((void**)&scx,  g_sc_x);  cudaGetSymbolAddress((void**)&scqw, g_sc_qw);
    cudaGetSymbolAddress((void**)&scwo, g_sc_wo); cudaGetSymbolAddress((void**)&scwu, g_sc_wu);
    cudaGetSymbolAddress((void**)&scwv, g_sc_wv); cudaGetSymbolAddress((void**)&scat, g_sc_at);
    cudaGetSymbolAddress((void**)&scx1, g_sc_x1); cudaGetSymbolAddress((void**)&scrs, g_sc_rs);

    cudaFuncSetAttribute(attn_kernel, cudaFuncAttributeMaxDynamicSharedMemorySize,
                         ATTN_SMEM_BYTES);
    cudaFuncSetAttribute(gemm_s8x3, cudaFuncAttributeMaxDynamicSharedMemorySize,
                         GSM_TOTAL);

    // 0) quantize input + weights
    quant_rows<<<ROWS, 256>>>(x, xh, xl, scx, DM);
    quant_rows<<<3 * DM, 256>>>(qkv, qwh, qwl, scqw, DM);
    quant_rows<<<DM, 256>>>(W_O, woh, wol, scwo, DM);
    quant_rows<<<8 * DM, 256>>>(Wu, wuh, wul, scwu, DM);
    quant_rows<<<DM, 256>>>(Wv, wvh, wvl, scwv, 4 * DM);

    // 1) QKV projection: [8192,3072] = x @ qkv^T
    gemm_s8x3<<<dim3(3 * DM / 128, ROWS / 128), 256, GSM_TOTAL>>>(
        xh, xl, qwh, qwl, scx, scqw, qkv_raw, ROWS, 3 * DM, DM);

    // 2) RoPE + justnorm + sqk scale
    rope_kernel<<<(Bz * Hz * Tz) / 4, 128>>>(sqk);

    // 3) causal attention
    attn_kernel<<<dim3(Tz / 64, Hz, Bz), 256, ATTN_SMEM_BYTES>>>();

    // 4) W_O projection
    quant_rows<<<ROWS, 256>>>(attnb, ath, atl, scat, DM);
    gemm_s8x3<<<dim3(DM / 128, ROWS / 128), 256, GSM_TOTAL>>>(
        ath, atl, woh, wol, scat, scwo, tb, ROWS, DM, DM);

    // 5) residual lerp #1 (coef = 0.05*sqrt(dm) = 1.6)
    resnorm_kernel<<<ROWS, 256>>>(x, tb, attn_alpha, 1.6f, x1b);

    // 6) Wu: uv = x1 @ Wu^T  [8192,8192]
    quant_rows<<<ROWS, 256>>>(x1b, x1h, x1l, scx1, DM);
    gemm_s8x3<<<dim3(8 * DM / 128, ROWS / 128), 256, GSM_TOTAL>>>(
        x1h, x1l, wuh, wul, scx1, scwu, uvb, ROWS, 8 * DM, DM);

    // 7) scale + full-vector justnorm + SwiGLU
    mlp_act_kernel<<<ROWS, 256>>>(suv);

    // 8) Wv: t = res @ Wv^T   (K = 4096)
    quant_rows<<<ROWS, 256>>>(resb, rsh, rsl, scrs, 4 * DM);
    gemm_s8x3<<<dim3(DM / 128, ROWS / 128), 256, GSM_TOTAL>>>(
        rsh, rsl, wvh, wvl, scrs, scwv, tb, ROWS, DM, 4 * DM);

    // 9) residual lerp #2 (coef = 0.05) -> final output
    resnorm_kernel<<<ROWS, 256>>>(x1b, tb, mlp_alpha, 0.05f, out);
}